// round 6
// baseline (speedup 1.0000x reference)
#include <cuda_runtime.h>

// AdditiveEmission: local-window (w=3) additive attention, fused single kernel.
//   q = X@Wt, k = X@Wx
//   e[i,j] = Wa . tanh(q_i + k_j + bh) + ba,  j in {i-1,i,i+1} (clipped)
//   a = softmax_window(e) (+EPS), out_i = sum_j a[i,j] * x_j
//
// B=4, L=512, D=128.
// Grid = 37 tiles x 4 batches = 148 blocks == #SMs (one perfect wave, no tail).
// Block: 256 threads = two 128-thread row-groups. Group g handles queries
// t in [7g, 7g+7) of a T=14 tile and computes its own 9 covering k-rows.
// Weight LDGs are front-batched 16 at a time (MLP ~16); group 1 hits L1.

#define B_    4
#define L_    512
#define D_    128
#define T_    14
#define TILES_ 37        // ceil(512/14)
#define RS_   16         // staged x rows: i0-1 .. i0+14
#define G_    7          // queries per group
#define KR_   9          // k rows per group
#define EPS_  1e-8f

__device__ __forceinline__ float tanh_approx(float v) {
    float r;
    asm("tanh.approx.f32 %0, %1;" : "=f"(r) : "f"(v));
    return r;
}

__global__ __launch_bounds__(256)
void additive_local_attn(const float* __restrict__ x,
                         const float* __restrict__ Wt,
                         const float* __restrict__ Wx,
                         const float* __restrict__ Wa,
                         const float* __restrict__ bh,
                         const float* __restrict__ ba,
                         float* __restrict__ out)
{
    __shared__ float xs[RS_][D_];     // rows i0-1 .. i0+T of x (zero-padded at ends)
    __shared__ float sred[T_][4][3];  // per-query, per-warp partial logit sums

    const int tid  = threadIdx.x;
    const int d    = tid & (D_ - 1);
    const int grp  = tid >> 7;          // 0 or 1
    const int lane = tid & 31;
    const int wig  = (tid >> 5) & 3;    // warp index within group
    const int b    = blockIdx.y;
    const int i0   = blockIdx.x * T_;

    const float* xb = x + (size_t)b * L_ * D_;

    // ---- stage x rows [i0-1, i0+T] into SMEM (groups interleave rows) ----
    #pragma unroll
    for (int r = grp; r < RS_; r += 2) {
        const int g = i0 - 1 + r;
        xs[r][d] = (g >= 0 && g < L_) ? xb[g * D_ + d] : 0.0f;
    }
    __syncthreads();

    // ---- fused GEMV over this group's rows ----
    // xs row (xbase + r) is k-row r of this group; q t_local uses xs row xbase+t+1.
    const int xbase = grp * G_;

    float qa[G_];
    float ka[KR_];
    #pragma unroll
    for (int t = 0; t < G_; ++t) qa[t] = 0.0f;
    #pragma unroll
    for (int r = 0; r < KR_; ++r) ka[r] = 0.0f;

    #pragma unroll 2
    for (int e = 0; e < D_; e += 8) {
        // front-batch 16 independent weight loads (high MLP)
        float wt[8], wx[8];
        #pragma unroll
        for (int u = 0; u < 8; ++u) {
            wt[u] = Wt[(e + u) * D_ + d];
            wx[u] = Wx[(e + u) * D_ + d];
        }
        #pragma unroll
        for (int r = 0; r < KR_; ++r) {
            const float4 xv0 = *reinterpret_cast<const float4*>(&xs[xbase + r][e]);
            const float4 xv1 = *reinterpret_cast<const float4*>(&xs[xbase + r][e + 4]);
            float kacc = ka[r];
            kacc = fmaf(xv0.x, wx[0], kacc);
            kacc = fmaf(xv0.y, wx[1], kacc);
            kacc = fmaf(xv0.z, wx[2], kacc);
            kacc = fmaf(xv0.w, wx[3], kacc);
            kacc = fmaf(xv1.x, wx[4], kacc);
            kacc = fmaf(xv1.y, wx[5], kacc);
            kacc = fmaf(xv1.z, wx[6], kacc);
            kacc = fmaf(xv1.w, wx[7], kacc);
            ka[r] = kacc;
            if (r >= 1 && r <= G_) {
                float qacc = qa[r - 1];
                qacc = fmaf(xv0.x, wt[0], qacc);
                qacc = fmaf(xv0.y, wt[1], qacc);
                qacc = fmaf(xv0.z, wt[2], qacc);
                qacc = fmaf(xv0.w, wt[3], qacc);
                qacc = fmaf(xv1.x, wt[4], qacc);
                qacc = fmaf(xv1.y, wt[5], qacc);
                qacc = fmaf(xv1.z, wt[6], qacc);
                qacc = fmaf(xv1.w, wt[7], qacc);
                qa[r - 1] = qacc;
            }
        }
    }

    // ---- logits: e_j(t) = sum_d Wa[d]*tanh(q[t][d] + k[t+j][d] + bh[d]) ----
    const float wad = Wa[d];
    const float bhd = bh[d];

    #pragma unroll
    for (int t = 0; t < G_; ++t) {
        float p0 = wad * tanh_approx(qa[t] + ka[t]     + bhd);
        float p1 = wad * tanh_approx(qa[t] + ka[t + 1] + bhd);
        float p2 = wad * tanh_approx(qa[t] + ka[t + 2] + bhd);
        #pragma unroll
        for (int off = 16; off; off >>= 1) {
            p0 += __shfl_xor_sync(0xffffffffu, p0, off);
            p1 += __shfl_xor_sync(0xffffffffu, p1, off);
            p2 += __shfl_xor_sync(0xffffffffu, p2, off);
        }
        if (lane == 0) {
            const int tg = xbase + t;   // global query index within tile
            sred[tg][wig][0] = p0;
            sred[tg][wig][1] = p1;
            sred[tg][wig][2] = p2;
        }
    }
    __syncthreads();

    // ---- windowed softmax (+EPS) and AV ----
    const float ba0 = ba[0];

    #pragma unroll
    for (int t = 0; t < G_; ++t) {
        const int tg = xbase + t;
        const int i  = i0 + tg;
        if (i >= L_) break;

        float e0 = sred[tg][0][0] + sred[tg][1][0] + sred[tg][2][0] + sred[tg][3][0] + ba0;
        float e1 = sred[tg][0][1] + sred[tg][1][1] + sred[tg][2][1] + sred[tg][3][1] + ba0;
        float e2 = sred[tg][0][2] + sred[tg][1][2] + sred[tg][2][2] + sred[tg][3][2] + ba0;

        const bool v0 = (i - 1) >= 0;
        const bool v2 = (i + 1) < L_;

        float m = e1;
        if (v0) m = fmaxf(m, e0);
        if (v2) m = fmaxf(m, e2);

        const float w0 = v0 ? __expf(e0 - m) : 0.0f;
        const float w1 = __expf(e1 - m);
        const float w2 = v2 ? __expf(e2 - m) : 0.0f;

        const float inv = 1.0f / (w0 + w1 + w2 + EPS_);
        const float o = (w0 * xs[tg][d] + w1 * xs[tg + 1][d] + w2 * xs[tg + 2][d]) * inv;
        out[(((size_t)b * L_ + i) * D_) + d] = o;
    }
}

extern "C" void kernel_launch(void* const* d_in, const int* in_sizes, int n_in,
                              void* d_out, int out_size)
{
    const float* x  = (const float*)d_in[0];
    const float* Wt = (const float*)d_in[1];
    const float* Wx = (const float*)d_in[2];
    const float* Wa = (const float*)d_in[3];
    const float* bh = (const float*)d_in[4];
    const float* ba = (const float*)d_in[5];
    float* out = (float*)d_out;

    dim3 grid(TILES_, B_);   // 37 x 4 = 148 blocks == #SMs
    additive_local_attn<<<grid, 256>>>(x, Wt, Wx, Wa, bh, ba, out);
}

// round 7
// speedup vs baseline: 1.0312x; 1.0312x over previous
#include <cuda_runtime.h>

// AdditiveEmission: local-window (w=3) additive attention, fused single kernel.
//   q = X@Wt, k = X@Wx
//   e[i,j] = Wa . tanh(q_i + k_j + bh) + ba,  j in {i-1,i,i+1} (clipped)
//   a = softmax_window(e) (+EPS), out_i = sum_j a[i,j] * x_j
//
// B=4, L=512, D=128.
// Grid = 37 tiles x 4 batches = 148 blocks == #SMs (one wave).
// Block = 512 threads = 4 cooperative groups of 128 (thread = channel d).
//   Phase 1: groups compute disjoint row-GEMVs ONCE (g0: q0-6, g1: q7-13,
//            g2: k0-7, g3: k8-15), each group loading only Wt OR Wx.
//   Phase 2: each group computes logits for 3-4 queries (tanh + warp reduce).
//   Phase 3: windowed softmax + AV, output.

#define B_     4
#define L_     512
#define D_     128
#define T_     14         // queries per tile
#define TILES_ 37         // ceil(512/14)
#define KR_    16         // k rows per tile: i0-1 .. i0+14
#define NQK_   (T_ + KR_) // 30 q/k rows in SMEM
#define EPS_   1e-8f

__device__ __forceinline__ float tanh_approx(float v) {
    float r;
    asm("tanh.approx.f32 %0, %1;" : "=f"(r) : "f"(v));
    return r;
}

// Phase-1 worker: NR row-GEMVs against weight matrix W, rows xs[xs0..xs0+NR),
// results to qk[dst0..dst0+NR). One thread = one output channel d.
template<int NR>
__device__ __forceinline__ void gemv_rows(const float (*xs)[D_], float (*qk)[D_],
                                          const float* __restrict__ W,
                                          int xs0, int dst0, int d)
{
    float acc[NR];
    #pragma unroll
    for (int r = 0; r < NR; ++r) acc[r] = 0.0f;

    #pragma unroll 2
    for (int e = 0; e < D_; e += 8) {
        float w[8];
        #pragma unroll
        for (int u = 0; u < 8; ++u) w[u] = W[(e + u) * D_ + d];   // coalesced, L1-shared
        #pragma unroll
        for (int r = 0; r < NR; ++r) {
            const float4 a = *reinterpret_cast<const float4*>(&xs[xs0 + r][e]);     // broadcast
            const float4 c = *reinterpret_cast<const float4*>(&xs[xs0 + r][e + 4]); // broadcast
            float s = acc[r];
            s = fmaf(a.x, w[0], s);
            s = fmaf(a.y, w[1], s);
            s = fmaf(a.z, w[2], s);
            s = fmaf(a.w, w[3], s);
            s = fmaf(c.x, w[4], s);
            s = fmaf(c.y, w[5], s);
            s = fmaf(c.z, w[6], s);
            s = fmaf(c.w, w[7], s);
            acc[r] = s;
        }
    }
    #pragma unroll
    for (int r = 0; r < NR; ++r) qk[dst0 + r][d] = acc[r];
}

__global__ __launch_bounds__(512, 1)
void additive_local_attn(const float* __restrict__ x,
                         const float* __restrict__ Wt,
                         const float* __restrict__ Wx,
                         const float* __restrict__ Wa,
                         const float* __restrict__ bh,
                         const float* __restrict__ ba,
                         float* __restrict__ out)
{
    __shared__ float xs[KR_][D_];      // x rows i0-1 .. i0+14 (zero-padded at ends)
    __shared__ float qk[NQK_][D_];     // rows 0..13: q[t]; rows 14..29: k[r]
    __shared__ float sred[T_][4][3];   // per-query per-warp partial logit sums

    const int tid  = threadIdx.x;
    const int d    = tid & (D_ - 1);
    const int grp  = tid >> 7;         // 0..3
    const int lane = tid & 31;
    const int wig  = (tid >> 5) & 3;   // warp within group
    const int b    = blockIdx.y;
    const int i0   = blockIdx.x * T_;

    const float* xb = x + (size_t)b * L_ * D_;

    // ---- stage x rows [i0-1, i0+14] ----
    #pragma unroll
    for (int r = grp; r < KR_; r += 4) {
        const int g = i0 - 1 + r;
        xs[r][d] = (g >= 0 && g < L_) ? xb[g * D_ + d] : 0.0f;
    }
    __syncthreads();

    // ---- phase 1: disjoint row-GEMVs (no redundancy) ----
    // g0: q rows 0-6   (xs 1-7,  dst 0)   weight Wt
    // g1: q rows 7-13  (xs 8-14, dst 7)   weight Wt
    // g2: k rows 0-7   (xs 0-7,  dst 14)  weight Wx
    // g3: k rows 8-15  (xs 8-15, dst 22)  weight Wx
    if (grp == 0)      gemv_rows<7>(xs, qk, Wt, 1, 0,  d);
    else if (grp == 1) gemv_rows<7>(xs, qk, Wt, 8, 7,  d);
    else if (grp == 2) gemv_rows<8>(xs, qk, Wx, 0, 14, d);
    else               gemv_rows<8>(xs, qk, Wx, 8, 22, d);
    __syncthreads();

    // ---- phase 2: logits for this group's queries ----
    // queries per group: g0: 0-3, g1: 4-7, g2: 8-10, g3: 11-13
    const int qstart = (grp == 0) ? 0 : (grp == 1) ? 4 : (grp == 2) ? 8 : 11;
    const int qcnt   = (grp < 2) ? 4 : 3;

    const float wad = Wa[d];
    const float bhd = bh[d];

    for (int u = 0; u < qcnt; ++u) {
        const int t = qstart + u;              // query t -> k rows t, t+1, t+2
        const float qv = qk[t][d] + bhd;
        float p0 = wad * tanh_approx(qv + qk[T_ + t][d]);
        float p1 = wad * tanh_approx(qv + qk[T_ + t + 1][d]);
        float p2 = wad * tanh_approx(qv + qk[T_ + t + 2][d]);
        #pragma unroll
        for (int off = 16; off; off >>= 1) {
            p0 += __shfl_xor_sync(0xffffffffu, p0, off);
            p1 += __shfl_xor_sync(0xffffffffu, p1, off);
            p2 += __shfl_xor_sync(0xffffffffu, p2, off);
        }
        if (lane == 0) {
            sred[t][wig][0] = p0;
            sred[t][wig][1] = p1;
            sred[t][wig][2] = p2;
        }
    }
    __syncthreads();

    // ---- phase 3: windowed softmax (+EPS) and AV for this group's queries ----
    const float ba0 = ba[0];

    for (int u = 0; u < qcnt; ++u) {
        const int t = qstart + u;
        const int i = i0 + t;
        if (i >= L_) break;

        float e0 = sred[t][0][0] + sred[t][1][0] + sred[t][2][0] + sred[t][3][0] + ba0;
        float e1 = sred[t][0][1] + sred[t][1][1] + sred[t][2][1] + sred[t][3][1] + ba0;
        float e2 = sred[t][0][2] + sred[t][1][2] + sred[t][2][2] + sred[t][3][2] + ba0;

        const bool v0 = (i - 1) >= 0;
        const bool v2 = (i + 1) < L_;

        float m = e1;
        if (v0) m = fmaxf(m, e0);
        if (v2) m = fmaxf(m, e2);

        const float w0 = v0 ? __expf(e0 - m) : 0.0f;
        const float w1 = __expf(e1 - m);
        const float w2 = v2 ? __expf(e2 - m) : 0.0f;

        const float inv = 1.0f / (w0 + w1 + w2 + EPS_);
        const float o = (w0 * xs[t][d] + w1 * xs[t + 1][d] + w2 * xs[t + 2][d]) * inv;
        out[(((size_t)b * L_ + i) * D_) + d] = o;
    }
}

extern "C" void kernel_launch(void* const* d_in, const int* in_sizes, int n_in,
                              void* d_out, int out_size)
{
    const float* x  = (const float*)d_in[0];
    const float* Wt = (const float*)d_in[1];
    const float* Wx = (const float*)d_in[2];
    const float* Wa = (const float*)d_in[3];
    const float* bh = (const float*)d_in[4];
    const float* ba = (const float*)d_in[5];
    float* out = (float*)d_out;

    dim3 grid(TILES_, B_);   // 37 x 4 = 148 blocks == #SMs
    additive_local_attn<<<grid, 512>>>(x, Wt, Wx, Wa, bh, ba, out);
}